// round 9
// baseline (speedup 1.0000x reference)
#include <cuda_runtime.h>
#include <cstdint>

// ---------------------------------------------------------------------------
// DiverseRegDCConv2d: per-sample dynamically-generated 3x3 conv.
//   wgen[b,o,c,kh,kw] = sum_n se[b,n] * weight[(o*C+c)*9+kh*3+kw, n]
//   out[b,o,h,w] = sum_{c,kh,kw} wgen[b,o,c,kh,kw] * x[b,c,h+kh-1,w+kw-1] + bias[o]
// B=32, C=O=256, H=W=28, K=3, NUM=8.
// ---------------------------------------------------------------------------

#define BB   32
#define CIN  256
#define COUT 256
#define HH   28
#define WW   28
#define NUMK 8
#define WROW 2304            // CIN*9 floats per output channel
#define NWG  589824          // COUT*WROW

__device__ float g_wgen[(size_t)BB * NWG];   // 75.5 MB generated weights

typedef unsigned long long ULL;

__device__ __forceinline__ ULL pack2(float lo, float hi) {
    ULL r; asm("mov.b64 %0, {%1, %2};" : "=l"(r) : "f"(lo), "f"(hi)); return r;
}
__device__ __forceinline__ ULL ffma2(ULL a, ULL b, ULL c) {
    ULL d; asm("fma.rn.f32x2 %0, %1, %2, %3;" : "=l"(d) : "l"(a), "l"(b), "l"(c)); return d;
}
__device__ __forceinline__ ULL fadd2(ULL a, ULL b) {
    ULL d; asm("add.rn.f32x2 %0, %1, %2;" : "=l"(d) : "l"(a), "l"(b)); return d;
}
__device__ __forceinline__ float2 unpack2(ULL v) {
    float2 f; asm("mov.b64 {%0, %1}, %2;" : "=f"(f.x), "=f"(f.y) : "l"(v)); return f;
}
__device__ __forceinline__ void cp16(uint32_t dst, const void* src) {
    asm volatile("cp.async.ca.shared.global [%0], [%1], 16;\n"
                 :: "r"(dst), "l"(src) : "memory");
}
__device__ __forceinline__ void cp4(uint32_t dst, const void* src) {
    asm volatile("cp.async.ca.shared.global [%0], [%1], 4;\n"
                 :: "r"(dst), "l"(src) : "memory");
}
#define CP_COMMIT() asm volatile("cp.async.commit_group;\n" ::: "memory")
#define CP_WAIT0()  asm volatile("cp.async.wait_group 0;\n" ::: "memory")

// ---------------------------------------------------------------------------
// Stage 1: weight generation (reads 18.9MB bank once, writes 75.5MB wgen)
// ---------------------------------------------------------------------------
__global__ void wgen_kernel(const float* __restrict__ wbank,
                            const float* __restrict__ se) {
    __shared__ float s_se[BB * NUMK];
    int tid = threadIdx.x;
    s_se[tid] = se[tid];
    __syncthreads();

    unsigned j = blockIdx.x * 256u + tid;
    const float4* w4 = (const float4*)wbank;
    float4 w0 = w4[2u * j];
    float4 w1 = w4[2u * j + 1u];

    #pragma unroll 4
    for (int b = 0; b < BB; ++b) {
        const float* s = &s_se[b * NUMK];
        float v = w0.x * s[0];
        v = fmaf(w0.y, s[1], v);
        v = fmaf(w0.z, s[2], v);
        v = fmaf(w0.w, s[3], v);
        v = fmaf(w1.x, s[4], v);
        v = fmaf(w1.y, s[5], v);
        v = fmaf(w1.z, s[6], v);
        v = fmaf(w1.w, s[7], v);
        g_wgen[(size_t)b * NWG + j] = v;
    }
}

// ---------------------------------------------------------------------------
// Stage 2: direct conv. Block (16,14)=224 thr: 32 o-channels x 7 rows.
// Thread: 1 o-channel x 1 row x 28 cols = 14 f32x2 accumulators.
// Input rows staged in SMEM in TWO alignments; ALL input reads are LDS.128
// (ulonglong2 = two FFMA2 operand pairs per instruction):
//   copy A: entry c   = col c  -> A2[jj] = pairs (Aq[2jj], Aq[2jj+1])
//   copy B: entry c+1 = col c  -> B2[jj] = pairs (Bq[2jj], Bq[2jj+1])
// where Aq[j]=cols(2j,2j+1) (tap kw=1), Bq[j]=cols(2j-1,2j) (tap kw=0),
// Bq[j+1]=cols(2j+1,2j+2) (tap kw=2).
// ---------------------------------------------------------------------------
#define CC   8               // channels per chunk
#define OT   32              // o-channels per block
#define RT   7               // output rows per block
#define NR   9               // input rows staged (RT + 2 halo)
#define WS_  76              // floats per o weight row (72 + pad, 16B mult)
#define XROW 64              // floats per staged row: A[32] | B[32]
#define WBUF (OT * WS_)      // 2432 floats per weight buffer
#define XBUF (CC * NR * XROW)// 4608 floats per input buffer
#define SMEM_BYTES ((2 * WBUF + 2 * XBUF) * 4)   // 19456 + 36864 = 56320 B

__global__ __launch_bounds__(224, 4)
void dconv_kernel(const float* __restrict__ x,
                  const float* __restrict__ bias,
                  float* __restrict__ out) {
    extern __shared__ float smem[];
    float* ws = smem;                  // [2][32][76] raw weights
    float* xs = smem + 2 * WBUF;       // [2][8][9][64] dual-aligned input rows

    const int tx  = threadIdx.x;       // 0..15
    const int ty  = threadIdx.y;       // 0..13
    const int tid = ty * 16 + tx;
    const int row = ty % 7;            // output row within block
    const int oh  = ty / 7;            // o half
    const int olocal = oh * 16 + tx;   // 0..31

    const int b       = blockIdx.y;
    const int ob      = blockIdx.x >> 2;   // 0..7
    const int rb      = blockIdx.x & 3;    // 0..3
    const int oBase   = ob * OT;
    const int rowBase = rb * RT;

    const float* wg = g_wgen + ((size_t)b * COUT + oBase) * WROW;
    const float* xb = x + (size_t)b * CIN * (HH * WW);

    const uint32_t ws_u = (uint32_t)__cvta_generic_to_shared(ws);
    const uint32_t xs_u = (uint32_t)__cvta_generic_to_shared(xs);

    // Zero both input buffers once: halo/pad entries stay zero forever.
    {
        float4* xz = (float4*)xs;
        for (int i = tid; i < (2 * XBUF) / 4; i += 224)
            xz[i] = make_float4(0.f, 0.f, 0.f, 0.f);
    }
    __syncthreads();

    ULL acc[14];
    #pragma unroll
    for (int j = 0; j < 14; ++j) acc[j] = 0ull;

    // ---- prologue: async-fill chunk 0 into buffer 0
    {
        for (int i = tid; i < OT * 18; i += 224) {          // weights, 16B
            int o = i / 18, ch = i % 18;
            cp16(ws_u + (o * WS_ + ch * 4) * 4,
                 wg + (size_t)o * WROW + ch * 4);
        }
        for (int i = tid; i < CC * NR * 7; i += 224) {      // copy A, 16B
            int cc = i / 63, rem = i % 63, rw = rem / 7, ch = rem % 7;
            int ih = rowBase - 1 + rw;
            if ((unsigned)ih < (unsigned)HH)
                cp16(xs_u + ((cc * NR + rw) * XROW + ch * 4) * 4,
                     xb + ((size_t)cc * HH + ih) * WW + ch * 4);
        }
        for (int i = tid; i < CC * NR * 28; i += 224) {     // copy B, 4B shifted
            int cc = i / 252, rem = i % 252, rw = rem / 28, c = rem % 28;
            int ih = rowBase - 1 + rw;
            if ((unsigned)ih < (unsigned)HH)
                cp4(xs_u + ((cc * NR + rw) * XROW + 32 + c + 1) * 4,
                    xb + ((size_t)cc * HH + ih) * WW + c);
        }
        CP_COMMIT();
    }

    for (int k = 0; k < CIN / CC; ++k) {
        CP_WAIT0();
        __syncthreads();

        if (k < CIN / CC - 1) {
            const int c0 = (k + 1) * CC;
            const uint32_t wd = ws_u + (((k + 1) & 1) * WBUF) * 4;
            const uint32_t xd = xs_u + (((k + 1) & 1) * XBUF) * 4;
            for (int i = tid; i < OT * 18; i += 224) {
                int o = i / 18, ch = i % 18;
                cp16(wd + (o * WS_ + ch * 4) * 4,
                     wg + (size_t)o * WROW + c0 * 9 + ch * 4);
            }
            for (int i = tid; i < CC * NR * 7; i += 224) {
                int cc = i / 63, rem = i % 63, rw = rem / 7, ch = rem % 7;
                int ih = rowBase - 1 + rw;
                if ((unsigned)ih < (unsigned)HH)
                    cp16(xd + ((cc * NR + rw) * XROW + ch * 4) * 4,
                         xb + ((size_t)(c0 + cc) * HH + ih) * WW + ch * 4);
            }
            for (int i = tid; i < CC * NR * 28; i += 224) {
                int cc = i / 252, rem = i % 252, rw = rem / 28, c = rem % 28;
                int ih = rowBase - 1 + rw;
                if ((unsigned)ih < (unsigned)HH)
                    cp4(xd + ((cc * NR + rw) * XROW + 32 + c + 1) * 4,
                        xb + ((size_t)(c0 + cc) * HH + ih) * WW + c);
            }
            CP_COMMIT();
        }

        const float* wsb = ws + (k & 1) * WBUF + olocal * WS_;
        const float* xsb = xs + (k & 1) * XBUF;

        for (int cc = 0; cc < CC; ++cc) {
            #pragma unroll
            for (int r = 0; r < 3; ++r) {
                const float* wp = wsb + cc * 9 + r * 3;
                float wv0 = wp[0], wv1 = wp[1], wv2 = wp[2];
                ULL w0 = pack2(wv0, wv0);
                ULL w1 = pack2(wv1, wv1);
                ULL w2 = pack2(wv2, wv2);
                const float* xr = xsb + (cc * NR + row + r) * XROW;
                const ulonglong2* A2 = (const ulonglong2*)xr;        // LDS.128
                const ulonglong2* B2 = (const ulonglong2*)(xr + 32); // LDS.128
                ULL btail = ((const ULL*)(xr + 32))[14];  // Bq[14] = (col27, 0)
                ulonglong2 bb = B2[0];
                #pragma unroll
                for (int jj = 0; jj < 7; ++jj) {
                    ulonglong2 a = A2[jj];
                    ulonglong2 bn;
                    ULL bhi2;                       // Bq[2jj+2]
                    if (jj < 6) { bn = B2[jj + 1]; bhi2 = bn.x; }
                    else        { bn.x = 0; bn.y = 0; bhi2 = btail; }
                    const int j0 = 2 * jj;
                    ULL t0  = ffma2(w0, bb.x, acc[j0]);     // taps (2j-1,2j)
                    t0      = ffma2(w1, a.x,  t0);          // taps (2j,  2j+1)
                    acc[j0] = ffma2(w2, bb.y, t0);          // taps (2j+1,2j+2)
                    ULL t1  = ffma2(w0, bb.y, acc[j0 + 1]);
                    t1      = ffma2(w1, a.y,  t1);
                    acc[j0 + 1] = ffma2(w2, bhi2, t1);
                    bb = bn;
                }
            }
        }
    }

    // ---- epilogue
    const int o = oBase + olocal;
    const int h = rowBase + row;
    float bv = bias[o];
    ULL bv2 = pack2(bv, bv);
    float2* op = (float2*)(out + (((size_t)b * COUT + o) * HH + h) * WW);
    #pragma unroll
    for (int j = 0; j < 14; ++j)
        op[j] = unpack2(fadd2(acc[j], bv2));
}

// ---------------------------------------------------------------------------
// Harness entry. Inputs (metadata order): inputs, inputs_se, weight, bias.
// ---------------------------------------------------------------------------
extern "C" void kernel_launch(void* const* d_in, const int* in_sizes, int n_in,
                              void* d_out, int out_size) {
    const float* x    = (const float*)d_in[0];   // [32,256,28,28]
    const float* se   = (const float*)d_in[1];   // [32,8]
    const float* wbk  = (const float*)d_in[2];   // [589824,8]
    const float* bias = (const float*)d_in[3];   // [256]
    float* out = (float*)d_out;                  // [32,256,28,28]

    cudaFuncSetAttribute(dconv_kernel,
                         cudaFuncAttributeMaxDynamicSharedMemorySize,
                         SMEM_BYTES);
    cudaFuncSetAttribute(dconv_kernel,
                         cudaFuncAttributePreferredSharedMemoryCarveout, 100);

    wgen_kernel<<<NWG / 256, 256>>>(wbk, se);

    dim3 grid(32, BB);          // x: 8 o-blocks * 4 row-blocks, y: batch
    dim3 block(16, 14);         // 224 threads
    dconv_kernel<<<grid, block, SMEM_BYTES>>>(x, bias, out);
}